// round 12
// baseline (speedup 1.0000x reference)
#include <cuda_runtime.h>
#include <cuda_fp16.h>
#include <cstdint>

// ============================================================================
// out[M,N] = float( sum_k x[m,k]*w[n,k] ) + rint(bias[n])
// M=8192, N=4096, K=4096.  Inputs delivered widened to int32.
// fp16 HMMA path: mma.sync.m16n8k16.f32; fp32 accumulation exact.
// R12: CTA tile 256x128 (512 thr, 1 CTA/SM, 4 stages) — 25% less cp.async +
// L2 traffic; cross-barrier fragment prefetch (stage ks+1 is wait_group-1
// complete during ks, so t=7 preloads its first LDSM fragments) removes the
// stage-start LDSM bubble.
// ============================================================================

#define K_DIM 4096
#define N_DIM 4096
#define M_DIM 8192
#define M_TILE 256
#define N_TILE 128
#define K_ELE  64                     // K elements per stage (= 128B rows)
#define STAGES 4
#define K_ITERS (K_DIM / K_ELE)       // 64
#define NTHREADS 512

#define A_STAGE_BYTES (M_TILE * 128)  // 32768
#define B_STAGE_BYTES (N_TILE * 128)  // 16384
#define SM_A 0
#define SM_B (STAGES * A_STAGE_BYTES)                 // 131072
#define SM_RBIAS (SM_B + STAGES * B_STAGE_BYTES)      // 196608
#define SMEM_TOTAL (SM_RBIAS + N_TILE * 4)            // 197120

__device__ __half g_xh[(size_t)M_DIM * K_DIM];        // 64 MB
__device__ __half g_wh[(size_t)N_DIM * K_DIM];        // 32 MB

// ---------------------------------------------------------------- helpers
__device__ __forceinline__ uint32_t smem_u32(const void* p) {
    uint32_t a;
    asm("{ .reg .u64 t; cvta.to.shared.u64 t, %1; cvt.u32.u64 %0, t; }"
        : "=r"(a) : "l"(p));
    return a;
}
__device__ __forceinline__ void cp16(uint32_t smem_dst, const void* gmem_src) {
    asm volatile("cp.async.cg.shared.global [%0], [%1], 16;"
                 :: "r"(smem_dst), "l"(gmem_src));
}
__device__ __forceinline__ void cp_commit() {
    asm volatile("cp.async.commit_group;" ::: "memory");
}
__device__ __forceinline__ void cp_wait1() {
    asm volatile("cp.async.wait_group 1;" ::: "memory");
}
__device__ __forceinline__ void cp_wait0() {
    asm volatile("cp.async.wait_group 0;" ::: "memory");
}
__device__ __forceinline__ void ldsm4(uint32_t r[4], uint32_t addr) {
    asm volatile("ldmatrix.sync.aligned.m8n8.x4.shared.b16 {%0,%1,%2,%3}, [%4];"
                 : "=r"(r[0]), "=r"(r[1]), "=r"(r[2]), "=r"(r[3])
                 : "r"(addr));
}
__device__ __forceinline__ void mma_f16(float d[4], const uint32_t a[4],
                                        uint32_t b0, uint32_t b1) {
    asm volatile(
        "mma.sync.aligned.m16n8k16.row.col.f32.f16.f16.f32 "
        "{%0,%1,%2,%3}, {%4,%5,%6,%7}, {%8,%9}, {%0,%1,%2,%3};"
        : "+f"(d[0]), "+f"(d[1]), "+f"(d[2]), "+f"(d[3])
        : "r"(a[0]), "r"(a[1]), "r"(a[2]), "r"(a[3]), "r"(b0), "r"(b1));
}

// ---------------------------------------------------------------- pack
__global__ void __launch_bounds__(256)
pack_s32_to_f16(const int* __restrict__ xsrc, const int* __restrict__ wsrc,
                __half* __restrict__ xdst, __half* __restrict__ wdst,
                int n8x, int n8_total) {
    int i = blockIdx.x * blockDim.x + threadIdx.x;
    if (i >= n8_total) return;
    const int* src; __half* dst; int idx;
    if (i < n8x) { src = xsrc; dst = xdst; idx = i; }
    else         { src = wsrc; dst = wdst; idx = i - n8x; }
    const int4* s = reinterpret_cast<const int4*>(src) + (size_t)idx * 2;
    int4 v0 = __ldg(&s[0]);
    int4 v1 = __ldg(&s[1]);
    uint32_t p[4];
    #define PK(lo_, hi_) \
        ((uint32_t)__half_as_ushort(__int2half_rn(lo_)) | \
         ((uint32_t)__half_as_ushort(__int2half_rn(hi_)) << 16))
    p[0] = PK(v0.x, v0.y);
    p[1] = PK(v0.z, v0.w);
    p[2] = PK(v1.x, v1.y);
    p[3] = PK(v1.z, v1.w);
    #undef PK
    reinterpret_cast<uint4*>(dst)[idx] = make_uint4(p[0], p[1], p[2], p[3]);
}

// ---------------------------------------------------------------- GEMM
// 16 warps: 4 in M (64 rows each) x 4 in N (32 cols each). Warp tile 64x32.
__global__ void __launch_bounds__(NTHREADS, 1)
w8a8_hmma_kernel(const float* __restrict__ bias, float* __restrict__ out) {
    extern __shared__ char smem[];
    const uint32_t sb = smem_u32(smem);
    const int tid  = threadIdx.x;
    const int wid  = tid >> 5;
    const int lane = tid & 31;

    const int n0 = blockIdx.x * N_TILE;
    const int m0 = blockIdx.y * M_TILE;

    float* rbias = reinterpret_cast<float*>(smem + SM_RBIAS);
    for (int j = tid; j < N_TILE; j += NTHREADS)
        rbias[j] = rintf(__ldg(&bias[n0 + j]));

    // ---- strength-reduced base addresses -------------------------------
    const int wm = (wid & 3) * 64;          // M offset within tile
    const int wn = (wid >> 2) * 32;         // N offset within tile
    const int lrow = lane & 15;
    const uint32_t x7    = (uint32_t)((lane & 7) << 4);
    const uint32_t lch16 = (uint32_t)((lane >> 4) << 4);

    const uint32_t aBase = sb + SM_A + (uint32_t)((wm + lrow) * 128);
    const uint32_t bBase = sb + SM_B + (uint32_t)((wn + lrow) * 128);

    // cp.async: 512 threads; thread handles rows row0 + 64i, fixed chunk c0
    const int row0 = tid >> 3, c0 = tid & 7;    // row0 in 0..63
    const uint32_t swz0 = (uint32_t)(row0 * 128 + ((c0 ^ (row0 & 7)) << 4));
    const uint32_t dstA0 = sb + SM_A + swz0;
    const uint32_t dstB0 = sb + SM_B + swz0;
    const __half* srcA0 = g_xh + (size_t)(m0 + row0) * K_DIM + c0 * 8;
    const __half* srcB0 = g_wh + (size_t)(n0 + row0) * K_DIM + c0 * 8;

    // per-i: 64 rows -> 8192B smem, 64*4096 halves gmem
    #define LOAD_STAGE_S(s_, kofs_) do {                                      \
        _Pragma("unroll")                                                     \
        for (int i_ = 0; i_ < 4; i_++)                                        \
            cp16(dstA0 + (uint32_t)((s_) * A_STAGE_BYTES + i_ * 8192),        \
                 srcA0 + (kofs_) + i_ * 262144);                              \
        _Pragma("unroll")                                                     \
        for (int i_ = 0; i_ < 2; i_++)                                        \
            cp16(dstB0 + (uint32_t)((s_) * B_STAGE_BYTES + i_ * 8192),        \
                 srcB0 + (kofs_) + i_ * 262144);                              \
        cp_commit();                                                          \
    } while (0)

    LOAD_STAGE_S(0, 0);
    LOAD_STAGE_S(1, K_ELE);
    LOAD_STAGE_S(2, 2 * K_ELE);

    float acc[4][4][4];
    #pragma unroll
    for (int mi = 0; mi < 4; mi++)
        #pragma unroll
        for (int ni = 0; ni < 4; ni++)
            #pragma unroll
            for (int r = 0; r < 4; r++) acc[mi][ni][r] = 0.f;

    uint32_t afr[2][2][4];
    uint32_t bfr[2][2][4];

    #define CX(kk_) ((((uint32_t)(kk_) << 5) | lch16) ^ x7)

    #define LOAD_A2(ab_, s_, kk_, half_) do {                                 \
        const uint32_t cx_ = CX(kk_);                                         \
        ldsm4(afr[ab_][0], aBase + cx_ +                                      \
              (uint32_t)((s_) * A_STAGE_BYTES + ((half_) * 2 + 0) * 2048));   \
        ldsm4(afr[ab_][1], aBase + cx_ +                                      \
              (uint32_t)((s_) * A_STAGE_BYTES + ((half_) * 2 + 1) * 2048));   \
    } while (0)
    #define LOAD_B2(bb_, s_, kk_) do {                                        \
        const uint32_t cx_ = CX(kk_);                                         \
        ldsm4(bfr[bb_][0], bBase + cx_ +                                      \
              (uint32_t)((s_) * B_STAGE_BYTES + 0 * 2048));                   \
        ldsm4(bfr[bb_][1], bBase + cx_ +                                      \
              (uint32_t)((s_) * B_STAGE_BYTES + 1 * 2048));                   \
    } while (0)

    // 8 (kk,half) sub-iterations; t=7 prefetches stage sn_'s first fragments
    // (valid: wait_group 1 + this iter's barrier made stage sn_ visible).
    #define PROCESS_STAGE(s_, sn_, pf_) do {                                  \
        _Pragma("unroll")                                                     \
        for (int t = 0; t < 8; t++) {                                         \
            const int kk   = t >> 1;                                          \
            const int half = t & 1;                                           \
            const int ab = t & 1;                                             \
            const int bb = kk & 1;                                            \
            if (t < 7) {                                                      \
                const int nkk = (t + 1) >> 1, nhalf = (t + 1) & 1;            \
                if (nhalf == 0) LOAD_B2((nkk & 1), s_, nkk);                  \
                LOAD_A2(ab ^ 1, s_, nkk, nhalf);                              \
            } else if (pf_) {                                                 \
                LOAD_B2(0, sn_, 0);                                           \
                LOAD_A2(0, sn_, 0, 0);                                        \
            }                                                                 \
            _Pragma("unroll")                                                 \
            for (int q = 0; q < 2; q++) {                                     \
                const int mi = half * 2 + q;                                  \
                _Pragma("unroll")                                             \
                for (int ni = 0; ni < 4; ni++)                                \
                    mma_f16(acc[mi][ni], afr[ab][q],                          \
                            bfr[bb][ni >> 1][ni & 1],                         \
                            bfr[bb][ni >> 1][(ni & 1) + 2]);                  \
            }                                                                 \
        }                                                                     \
    } while (0)

    int kload = 3 * K_ELE;                  // element offset of next prefetch
    for (int kb = 0; kb < K_ITERS / 4; kb++) {      // 16 blocks of 4 stages
        #pragma unroll
        for (int j = 0; j < 4; j++) {
            const int ks = kb * 4 + j;
            if (ks >= 62) cp_wait0(); else cp_wait1();
            __syncthreads();
            if (kload < K_DIM) {
                LOAD_STAGE_S((j + 3) & 3, kload);
                kload += K_ELE;
            }
            if (ks == 0) {                  // initial fragment load (stage 0)
                LOAD_B2(0, 0, 0);
                LOAD_A2(0, 0, 0, 0);
            }
            PROCESS_STAGE(j, (j + 1) & 3, ks < 63);
        }
    }

    // epilogue: c0,c1 at (row=lane>>2, col=(lane&3)*2+{0,1}); c2,c3 at row+8
    const int erow = lane >> 2;
    const int ecol = (lane & 3) * 2;
    #pragma unroll
    for (int mi = 0; mi < 4; mi++) {
        #pragma unroll
        for (int ni = 0; ni < 4; ni++) {
            const int gc = wn + ni * 8 + ecol;
            const float b0 = rbias[gc], b1 = rbias[gc + 1];
            {
                const int gr = m0 + wm + mi * 16 + erow;
                float2 v;
                v.x = acc[mi][ni][0] + b0;
                v.y = acc[mi][ni][1] + b1;
                *reinterpret_cast<float2*>(out + (size_t)gr * N_DIM + n0 + gc) = v;
            }
            {
                const int gr = m0 + wm + mi * 16 + 8 + erow;
                float2 v;
                v.x = acc[mi][ni][2] + b0;
                v.y = acc[mi][ni][3] + b1;
                *reinterpret_cast<float2*>(out + (size_t)gr * N_DIM + n0 + gc) = v;
            }
        }
    }
}

// ---------------------------------------------------------------- launch
extern "C" void kernel_launch(void* const* d_in, const int* in_sizes, int n_in,
                              void* d_out, int out_size) {
    int xi = 0, bi = 0;
    for (int i = 1; i < n_in; i++) {
        if (in_sizes[i] > in_sizes[xi]) xi = i;
        if (in_sizes[i] < in_sizes[bi]) bi = i;
    }
    int wi = 3 - xi - bi;

    const int*   x32  = (const int*)d_in[xi];
    const int*   w32  = (const int*)d_in[wi];
    const float* bias = (const float*)d_in[bi];
    float* out = (float*)d_out;

    __half* xh = nullptr; cudaGetSymbolAddress((void**)&xh, g_xh);
    __half* wh = nullptr; cudaGetSymbolAddress((void**)&wh, g_wh);

    const int n8x = (M_DIM * K_DIM) / 8;
    const int n8w = (N_DIM * K_DIM) / 8;
    const int n8t = n8x + n8w;
    pack_s32_to_f16<<<(n8t + 255) / 256, 256>>>(x32, w32, xh, wh, n8x, n8t);

    cudaFuncSetAttribute(w8a8_hmma_kernel,
                         cudaFuncAttributeMaxDynamicSharedMemorySize, SMEM_TOTAL);

    dim3 grid(N_DIM / N_TILE, M_DIM / M_TILE);         // (32, 32) = 1024 CTAs
    w8a8_hmma_kernel<<<grid, NTHREADS, SMEM_TOTAL>>>(bias, out);
}

// round 13
// speedup vs baseline: 1.0576x; 1.0576x over previous
#include <cuda_runtime.h>
#include <cuda_fp16.h>
#include <cstdint>

// ============================================================================
// out[M,N] = float( sum_k x[m,k]*w[n,k] ) + rint(bias[n])
// M=8192, N=4096, K=4096.  Inputs delivered widened to int32.
// fp16 HMMA path: mma.sync.m16n8k16.f32; fp32 accumulation exact.
// R13: R11 tile (128x128, 256 thr, 2 CTA/SM, 3 stages) + (a) race-free
// cross-barrier fragment prefetch: wait_group 0 before the barrier makes
// stage ks+1 complete AND barrier-published during iter ks, so t=7 preloads
// its first LDSM fragments; (b) per-warp k16 rotation decorrelates the
// post-barrier LDS burst across the 4 warps of an SMSP (exact reorder).
// ============================================================================

#define K_DIM 4096
#define N_DIM 4096
#define M_DIM 8192
#define M_TILE 128
#define N_TILE 128
#define K_ELE  64                     // K elements per stage (= 128B rows)
#define STAGES 3
#define K_ITERS (K_DIM / K_ELE)       // 64
#define NTHREADS 256

#define A_STAGE_BYTES (M_TILE * 128)  // 16384
#define B_STAGE_BYTES (N_TILE * 128)  // 16384
#define SM_A 0
#define SM_B (STAGES * A_STAGE_BYTES)                 // 49152
#define SM_RBIAS (SM_B + STAGES * B_STAGE_BYTES)      // 98304
#define SMEM_TOTAL (SM_RBIAS + N_TILE * 4)            // 98816

__device__ __half g_xh[(size_t)M_DIM * K_DIM];        // 64 MB
__device__ __half g_wh[(size_t)N_DIM * K_DIM];        // 32 MB

// ---------------------------------------------------------------- helpers
__device__ __forceinline__ uint32_t smem_u32(const void* p) {
    uint32_t a;
    asm("{ .reg .u64 t; cvta.to.shared.u64 t, %1; cvt.u32.u64 %0, t; }"
        : "=r"(a) : "l"(p));
    return a;
}
__device__ __forceinline__ void cp16(uint32_t smem_dst, const void* gmem_src) {
    asm volatile("cp.async.cg.shared.global [%0], [%1], 16;"
                 :: "r"(smem_dst), "l"(gmem_src));
}
__device__ __forceinline__ void cp_commit() {
    asm volatile("cp.async.commit_group;" ::: "memory");
}
__device__ __forceinline__ void cp_wait0() {
    asm volatile("cp.async.wait_group 0;" ::: "memory");
}
__device__ __forceinline__ void ldsm4(uint32_t r[4], uint32_t addr) {
    asm volatile("ldmatrix.sync.aligned.m8n8.x4.shared.b16 {%0,%1,%2,%3}, [%4];"
                 : "=r"(r[0]), "=r"(r[1]), "=r"(r[2]), "=r"(r[3])
                 : "r"(addr));
}
__device__ __forceinline__ void mma_f16(float d[4], const uint32_t a[4],
                                        uint32_t b0, uint32_t b1) {
    asm volatile(
        "mma.sync.aligned.m16n8k16.row.col.f32.f16.f16.f32 "
        "{%0,%1,%2,%3}, {%4,%5,%6,%7}, {%8,%9}, {%0,%1,%2,%3};"
        : "+f"(d[0]), "+f"(d[1]), "+f"(d[2]), "+f"(d[3])
        : "r"(a[0]), "r"(a[1]), "r"(a[2]), "r"(a[3]), "r"(b0), "r"(b1));
}

// ---------------------------------------------------------------- pack
__global__ void __launch_bounds__(256)
pack_s32_to_f16(const int* __restrict__ xsrc, const int* __restrict__ wsrc,
                __half* __restrict__ xdst, __half* __restrict__ wdst,
                int n8x, int n8_total) {
    int i = blockIdx.x * blockDim.x + threadIdx.x;
    if (i >= n8_total) return;
    const int* src; __half* dst; int idx;
    if (i < n8x) { src = xsrc; dst = xdst; idx = i; }
    else         { src = wsrc; dst = wdst; idx = i - n8x; }
    const int4* s = reinterpret_cast<const int4*>(src) + (size_t)idx * 2;
    int4 v0 = __ldg(&s[0]);
    int4 v1 = __ldg(&s[1]);
    uint32_t p[4];
    #define PK(lo_, hi_) \
        ((uint32_t)__half_as_ushort(__int2half_rn(lo_)) | \
         ((uint32_t)__half_as_ushort(__int2half_rn(hi_)) << 16))
    p[0] = PK(v0.x, v0.y);
    p[1] = PK(v0.z, v0.w);
    p[2] = PK(v1.x, v1.y);
    p[3] = PK(v1.z, v1.w);
    #undef PK
    reinterpret_cast<uint4*>(dst)[idx] = make_uint4(p[0], p[1], p[2], p[3]);
}

// ---------------------------------------------------------------- GEMM
// 8 warps: 2 in M (64 rows) x 4 in N (32 cols).  Warp tile 64x32.
__global__ void __launch_bounds__(NTHREADS, 2)
w8a8_hmma_kernel(const float* __restrict__ bias, float* __restrict__ out) {
    extern __shared__ char smem[];
    const uint32_t sb = smem_u32(smem);
    const int tid  = threadIdx.x;
    const int wid  = tid >> 5;
    const int lane = tid & 31;

    const int n0 = blockIdx.x * N_TILE;
    const int m0 = blockIdx.y * M_TILE;

    float* rbias = reinterpret_cast<float*>(smem + SM_RBIAS);
    for (int j = tid; j < N_TILE; j += NTHREADS)
        rbias[j] = rintf(__ldg(&bias[n0 + j]));

    // ---- strength-reduced base addresses -------------------------------
    const int wm = (wid & 1) * 64;
    const int wn = (wid >> 1) * 32;
    const int lrow = lane & 15;
    const uint32_t x7    = (uint32_t)((lane & 7) << 4);
    const uint32_t lch16 = (uint32_t)((lane >> 4) << 4);

    const uint32_t aBase = sb + SM_A + (uint32_t)((wm + lrow) * 128);
    const uint32_t bBase = sb + SM_B + (uint32_t)((wn + lrow) * 128);

    // per-warp k16 rotation: warp processes logical kk j as physical
    // kk = (j + rot) & 3; addition reorder only -> result exact.
    const int rot = wid & 3;
    uint32_t cxr[4];
    #pragma unroll
    for (int j = 0; j < 4; j++)
        cxr[j] = ((((uint32_t)((j + rot) & 3)) << 5) | lch16) ^ x7;

    // cp.async bases: thread handles rows row0+32i, fixed chunk c0
    const int row0 = tid >> 3, c0 = tid & 7;
    const uint32_t swz0 = (uint32_t)(row0 * 128 + ((c0 ^ (row0 & 7)) << 4));
    const uint32_t dstA0 = sb + SM_A + swz0;
    const uint32_t dstB0 = sb + SM_B + swz0;
    const __half* srcA0 = g_xh + (size_t)(m0 + row0) * K_DIM + c0 * 8;
    const __half* srcB0 = g_wh + (size_t)(n0 + row0) * K_DIM + c0 * 8;

    #define LOAD_STAGE_S(s_, kofs_) do {                                      \
        _Pragma("unroll")                                                     \
        for (int i_ = 0; i_ < 4; i_++)                                        \
            cp16(dstA0 + (uint32_t)((s_) * A_STAGE_BYTES + i_ * 4096),        \
                 srcA0 + (kofs_) + i_ * 131072);                              \
        _Pragma("unroll")                                                     \
        for (int i_ = 0; i_ < 4; i_++)                                        \
            cp16(dstB0 + (uint32_t)((s_) * B_STAGE_BYTES + i_ * 4096),        \
                 srcB0 + (kofs_) + i_ * 131072);                              \
        cp_commit();                                                          \
    } while (0)

    LOAD_STAGE_S(0, 0);
    LOAD_STAGE_S(1, K_ELE);

    float acc[4][4][4];
    #pragma unroll
    for (int mi = 0; mi < 4; mi++)
        #pragma unroll
        for (int ni = 0; ni < 4; ni++)
            #pragma unroll
            for (int r = 0; r < 4; r++) acc[mi][ni][r] = 0.f;

    uint32_t afr[2][2][4];
    uint32_t bfr[2][2][4];

    // fragment loads for LOGICAL k16 index j (physical kk baked into cxr[j])
    #define LOAD_A2(ab_, s_, j_, half_) do {                                  \
        ldsm4(afr[ab_][0], aBase + cxr[j_] +                                  \
              (uint32_t)((s_) * A_STAGE_BYTES + ((half_) * 2 + 0) * 2048));   \
        ldsm4(afr[ab_][1], aBase + cxr[j_] +                                  \
              (uint32_t)((s_) * A_STAGE_BYTES + ((half_) * 2 + 1) * 2048));   \
    } while (0)
    #define LOAD_B2(bb_, s_, j_) do {                                         \
        ldsm4(bfr[bb_][0], bBase + cxr[j_] +                                  \
              (uint32_t)((s_) * B_STAGE_BYTES + 0 * 2048));                   \
        ldsm4(bfr[bb_][1], bBase + cxr[j_] +                                  \
              (uint32_t)((s_) * B_STAGE_BYTES + 1 * 2048));                   \
    } while (0)

    // 8 (kk,half) sub-iterations; t=7 prefetches stage sn_'s first fragments
    // (stage sn_ is wait0-complete AND barrier-published at this point).
    #define PROCESS_STAGE(s_, sn_, pf_) do {                                  \
        _Pragma("unroll")                                                     \
        for (int t = 0; t < 8; t++) {                                         \
            const int kk   = t >> 1;                                          \
            const int half = t & 1;                                           \
            const int ab = t & 1;                                             \
            const int bb = kk & 1;                                            \
            if (t < 7) {                                                      \
                const int nkk = (t + 1) >> 1, nhalf = (t + 1) & 1;            \
                if (nhalf == 0) LOAD_B2((nkk & 1), s_, nkk);                  \
                LOAD_A2(ab ^ 1, s_, nkk, nhalf);                              \
            } else if (pf_) {                                                 \
                LOAD_B2(0, sn_, 0);                                           \
                LOAD_A2(0, sn_, 0, 0);                                        \
            }                                                                 \
            _Pragma("unroll")                                                 \
            for (int q = 0; q < 2; q++) {                                     \
                const int mi = half * 2 + q;                                  \
                _Pragma("unroll")                                             \
                for (int ni = 0; ni < 4; ni++)                                \
                    mma_f16(acc[mi][ni], afr[ab][q],                          \
                            bfr[bb][ni >> 1][ni & 1],                         \
                            bfr[bb][ni >> 1][(ni & 1) + 2]);                  \
            }                                                                 \
        }                                                                     \
    } while (0)

    // main loop unrolled by 3: stage indices are compile-time constants.
    // Per iter: wait0 (all issued groups complete) -> barrier (publish) ->
    // issue next load -> process current stage (t=7 prefetches next stage).
    int kload = 2 * K_ELE;
    for (int kb = 0; kb < (K_ITERS - 1) / 3; kb++) {   // 21 blocks = ks 0..62
        #pragma unroll
        for (int j = 0; j < 3; j++) {
            const int ks = kb * 3 + j;
            cp_wait0();
            __syncthreads();
            if (kload < K_DIM) {
                LOAD_STAGE_S((j + 2) % 3, kload);
                kload += K_ELE;
            }
            if (ks == 0) {                  // initial fragment load (stage 0)
                LOAD_B2(0, 0, 0);
                LOAD_A2(0, 0, 0, 0);
            }
            PROCESS_STAGE(j, (j + 1) % 3, 1);
        }
    }
    // tail: ks = 63, stage 0 (63 % 3)
    cp_wait0();
    __syncthreads();
    PROCESS_STAGE(0, 1, 0);

    // epilogue: c0,c1 at (row=lane>>2, col=(lane&3)*2+{0,1}); c2,c3 at row+8
    const int erow = lane >> 2;
    const int ecol = (lane & 3) * 2;
    #pragma unroll
    for (int mi = 0; mi < 4; mi++) {
        #pragma unroll
        for (int ni = 0; ni < 4; ni++) {
            const int gc = wn + ni * 8 + ecol;
            const float b0 = rbias[gc], b1 = rbias[gc + 1];
            {
                const int gr = m0 + wm + mi * 16 + erow;
                float2 v;
                v.x = acc[mi][ni][0] + b0;
                v.y = acc[mi][ni][1] + b1;
                *reinterpret_cast<float2*>(out + (size_t)gr * N_DIM + n0 + gc) = v;
            }
            {
                const int gr = m0 + wm + mi * 16 + 8 + erow;
                float2 v;
                v.x = acc[mi][ni][2] + b0;
                v.y = acc[mi][ni][3] + b1;
                *reinterpret_cast<float2*>(out + (size_t)gr * N_DIM + n0 + gc) = v;
            }
        }
    }
}

// ---------------------------------------------------------------- launch
extern "C" void kernel_launch(void* const* d_in, const int* in_sizes, int n_in,
                              void* d_out, int out_size) {
    int xi = 0, bi = 0;
    for (int i = 1; i < n_in; i++) {
        if (in_sizes[i] > in_sizes[xi]) xi = i;
        if (in_sizes[i] < in_sizes[bi]) bi = i;
    }
    int wi = 3 - xi - bi;

    const int*   x32  = (const int*)d_in[xi];
    const int*   w32  = (const int*)d_in[wi];
    const float* bias = (const float*)d_in[bi];
    float* out = (float*)d_out;

    __half* xh = nullptr; cudaGetSymbolAddress((void**)&xh, g_xh);
    __half* wh = nullptr; cudaGetSymbolAddress((void**)&wh, g_wh);

    const int n8x = (M_DIM * K_DIM) / 8;
    const int n8w = (N_DIM * K_DIM) / 8;
    const int n8t = n8x + n8w;
    pack_s32_to_f16<<<(n8t + 255) / 256, 256>>>(x32, w32, xh, wh, n8x, n8t);

    cudaFuncSetAttribute(w8a8_hmma_kernel,
                         cudaFuncAttributeMaxDynamicSharedMemorySize, SMEM_TOTAL);

    dim3 grid(N_DIM / N_TILE, M_DIM / M_TILE);         // (32, 64) = 2048 CTAs
    w8a8_hmma_kernel<<<grid, NTHREADS, SMEM_TOTAL>>>(bias, out);
}

// round 14
// speedup vs baseline: 1.0688x; 1.0106x over previous
#include <cuda_runtime.h>
#include <cuda_fp16.h>
#include <cstdint>

// ============================================================================
// out[M,N] = float( sum_k x[m,k]*w[n,k] ) + rint(bias[n])
// M=8192, N=4096, K=4096.  Inputs delivered widened to int32.
// fp16 HMMA path: mma.sync.m16n8k16.f32 (rt_SMSP=8); fp32 accumulation exact.
// R14: late-barrier stage structure — t=0..5 (48 MMAs) run BEFORE
// cp_wait0/__syncthreads (they only read the already-published stage and
// registers); the barrier + cp.async burst sit in front of just t=6..7,
// whose MMAs overlap the LSU burst. Keeps R13's cross-barrier t0 prefetch
// and per-warp kk rotation.
// ============================================================================

#define K_DIM 4096
#define N_DIM 4096
#define M_DIM 8192
#define M_TILE 128
#define N_TILE 128
#define K_ELE  64                     // K elements per stage (= 128B rows)
#define STAGES 3
#define K_ITERS (K_DIM / K_ELE)       // 64
#define NTHREADS 256

#define A_STAGE_BYTES (M_TILE * 128)  // 16384
#define B_STAGE_BYTES (N_TILE * 128)  // 16384
#define SM_A 0
#define SM_B (STAGES * A_STAGE_BYTES)                 // 49152
#define SM_RBIAS (SM_B + STAGES * B_STAGE_BYTES)      // 98304
#define SMEM_TOTAL (SM_RBIAS + N_TILE * 4)            // 98816

__device__ __half g_xh[(size_t)M_DIM * K_DIM];        // 64 MB
__device__ __half g_wh[(size_t)N_DIM * K_DIM];        // 32 MB

// ---------------------------------------------------------------- helpers
__device__ __forceinline__ uint32_t smem_u32(const void* p) {
    uint32_t a;
    asm("{ .reg .u64 t; cvta.to.shared.u64 t, %1; cvt.u32.u64 %0, t; }"
        : "=r"(a) : "l"(p));
    return a;
}
__device__ __forceinline__ void cp16(uint32_t smem_dst, const void* gmem_src) {
    asm volatile("cp.async.cg.shared.global [%0], [%1], 16;"
                 :: "r"(smem_dst), "l"(gmem_src));
}
__device__ __forceinline__ void cp_commit() {
    asm volatile("cp.async.commit_group;" ::: "memory");
}
__device__ __forceinline__ void cp_wait0() {
    asm volatile("cp.async.wait_group 0;" ::: "memory");
}
__device__ __forceinline__ void ldsm4(uint32_t r[4], uint32_t addr) {
    asm volatile("ldmatrix.sync.aligned.m8n8.x4.shared.b16 {%0,%1,%2,%3}, [%4];"
                 : "=r"(r[0]), "=r"(r[1]), "=r"(r[2]), "=r"(r[3])
                 : "r"(addr));
}
__device__ __forceinline__ void mma_f16(float d[4], const uint32_t a[4],
                                        uint32_t b0, uint32_t b1) {
    asm volatile(
        "mma.sync.aligned.m16n8k16.row.col.f32.f16.f16.f32 "
        "{%0,%1,%2,%3}, {%4,%5,%6,%7}, {%8,%9}, {%0,%1,%2,%3};"
        : "+f"(d[0]), "+f"(d[1]), "+f"(d[2]), "+f"(d[3])
        : "r"(a[0]), "r"(a[1]), "r"(a[2]), "r"(a[3]), "r"(b0), "r"(b1));
}

// ---------------------------------------------------------------- pack
__global__ void __launch_bounds__(256)
pack_s32_to_f16(const int* __restrict__ xsrc, const int* __restrict__ wsrc,
                __half* __restrict__ xdst, __half* __restrict__ wdst,
                int n8x, int n8_total) {
    int i = blockIdx.x * blockDim.x + threadIdx.x;
    if (i >= n8_total) return;
    const int* src; __half* dst; int idx;
    if (i < n8x) { src = xsrc; dst = xdst; idx = i; }
    else         { src = wsrc; dst = wdst; idx = i - n8x; }
    const int4* s = reinterpret_cast<const int4*>(src) + (size_t)idx * 2;
    int4 v0 = __ldg(&s[0]);
    int4 v1 = __ldg(&s[1]);
    uint32_t p[4];
    #define PK(lo_, hi_) \
        ((uint32_t)__half_as_ushort(__int2half_rn(lo_)) | \
         ((uint32_t)__half_as_ushort(__int2half_rn(hi_)) << 16))
    p[0] = PK(v0.x, v0.y);
    p[1] = PK(v0.z, v0.w);
    p[2] = PK(v1.x, v1.y);
    p[3] = PK(v1.z, v1.w);
    #undef PK
    reinterpret_cast<uint4*>(dst)[idx] = make_uint4(p[0], p[1], p[2], p[3]);
}

// ---------------------------------------------------------------- GEMM
// 8 warps: 2 in M (64 rows) x 4 in N (32 cols).  Warp tile 64x32.
__global__ void __launch_bounds__(NTHREADS, 2)
w8a8_hmma_kernel(const float* __restrict__ bias, float* __restrict__ out) {
    extern __shared__ char smem[];
    const uint32_t sb = smem_u32(smem);
    const int tid  = threadIdx.x;
    const int wid  = tid >> 5;
    const int lane = tid & 31;

    const int n0 = blockIdx.x * N_TILE;
    const int m0 = blockIdx.y * M_TILE;

    float* rbias = reinterpret_cast<float*>(smem + SM_RBIAS);
    for (int j = tid; j < N_TILE; j += NTHREADS)
        rbias[j] = rintf(__ldg(&bias[n0 + j]));

    // ---- strength-reduced base addresses -------------------------------
    const int wm = (wid & 1) * 64;
    const int wn = (wid >> 1) * 32;
    const int lrow = lane & 15;
    const uint32_t x7    = (uint32_t)((lane & 7) << 4);
    const uint32_t lch16 = (uint32_t)((lane >> 4) << 4);

    const uint32_t aBase = sb + SM_A + (uint32_t)((wm + lrow) * 128);
    const uint32_t bBase = sb + SM_B + (uint32_t)((wn + lrow) * 128);

    // per-warp k16 rotation (exact addition reorder)
    const int rot = wid & 3;
    uint32_t cxr[4];
    #pragma unroll
    for (int j = 0; j < 4; j++)
        cxr[j] = ((((uint32_t)((j + rot) & 3)) << 5) | lch16) ^ x7;

    // cp.async bases
    const int row0 = tid >> 3, c0 = tid & 7;
    const uint32_t swz0 = (uint32_t)(row0 * 128 + ((c0 ^ (row0 & 7)) << 4));
    const uint32_t dstA0 = sb + SM_A + swz0;
    const uint32_t dstB0 = sb + SM_B + swz0;
    const __half* srcA0 = g_xh + (size_t)(m0 + row0) * K_DIM + c0 * 8;
    const __half* srcB0 = g_wh + (size_t)(n0 + row0) * K_DIM + c0 * 8;

    #define LOAD_STAGE_S(s_, kofs_) do {                                      \
        _Pragma("unroll")                                                     \
        for (int i_ = 0; i_ < 4; i_++)                                        \
            cp16(dstA0 + (uint32_t)((s_) * A_STAGE_BYTES + i_ * 4096),        \
                 srcA0 + (kofs_) + i_ * 131072);                              \
        _Pragma("unroll")                                                     \
        for (int i_ = 0; i_ < 4; i_++)                                        \
            cp16(dstB0 + (uint32_t)((s_) * B_STAGE_BYTES + i_ * 4096),        \
                 srcB0 + (kofs_) + i_ * 131072);                              \
        cp_commit();                                                          \
    } while (0)

    float acc[4][4][4];
    #pragma unroll
    for (int mi = 0; mi < 4; mi++)
        #pragma unroll
        for (int ni = 0; ni < 4; ni++)
            #pragma unroll
            for (int r = 0; r < 4; r++) acc[mi][ni][r] = 0.f;

    uint32_t afr[2][2][4];
    uint32_t bfr[2][2][4];

    #define LOAD_A2(ab_, s_, j_, half_) do {                                  \
        ldsm4(afr[ab_][0], aBase + cxr[j_] +                                  \
              (uint32_t)((s_) * A_STAGE_BYTES + ((half_) * 2 + 0) * 2048));   \
        ldsm4(afr[ab_][1], aBase + cxr[j_] +                                  \
              (uint32_t)((s_) * A_STAGE_BYTES + ((half_) * 2 + 1) * 2048));   \
    } while (0)
    #define LOAD_B2(bb_, s_, j_) do {                                         \
        ldsm4(bfr[bb_][0], bBase + cxr[j_] +                                  \
              (uint32_t)((s_) * B_STAGE_BYTES + 0 * 2048));                   \
        ldsm4(bfr[bb_][1], bBase + cxr[j_] +                                  \
              (uint32_t)((s_) * B_STAGE_BYTES + 1 * 2048));                   \
    } while (0)

    // one (kk,half) sub-iteration: prefetch t+1 frags (t<7) or next-stage t0
    // frags (t==7, pf), then 8 MMAs.
    #define SUBIT(t_, s_, sn_, pf_) do {                                      \
        const int kk_   = (t_) >> 1;                                          \
        const int half_ = (t_) & 1;                                           \
        const int ab_ = (t_) & 1;                                             \
        const int bb_ = kk_ & 1;                                              \
        if ((t_) < 7) {                                                       \
            const int nkk_ = ((t_) + 1) >> 1, nhalf_ = ((t_) + 1) & 1;        \
            if (nhalf_ == 0) LOAD_B2((nkk_ & 1), s_, nkk_);                   \
            LOAD_A2(ab_ ^ 1, s_, nkk_, nhalf_);                               \
        } else if (pf_) {                                                     \
            LOAD_B2(0, sn_, 0);                                               \
            LOAD_A2(0, sn_, 0, 0);                                            \
        }                                                                     \
        _Pragma("unroll")                                                     \
        for (int q_ = 0; q_ < 2; q_++) {                                      \
            const int mi_ = half_ * 2 + q_;                                   \
            _Pragma("unroll")                                                 \
            for (int ni_ = 0; ni_ < 4; ni_++)                                 \
                mma_f16(acc[mi_][ni_], afr[ab_][q_],                          \
                        bfr[bb_][ni_ >> 1][ni_ & 1],                          \
                        bfr[bb_][ni_ >> 1][(ni_ & 1) + 2]);                   \
        }                                                                     \
    } while (0)

    // ---- prologue: stages 0,1 in flight; stage-0 t0 fragments in regs ----
    LOAD_STAGE_S(0, 0);
    LOAD_STAGE_S(1, K_ELE);
    cp_wait0();
    __syncthreads();
    LOAD_B2(0, 0, 0);
    LOAD_A2(0, 0, 0, 0);

    // ---- main loop: ks = 0..62 (unrolled by 3), tail ks = 63 -------------
    // Late barrier: t=0..5 read only stage ks (published last iter) and
    // registers; wait0+sync protect the cp16 overwrite of stage ks+2 and
    // the t=7 prefetch of stage ks+1.
    int kload = 2 * K_ELE;
    for (int kb = 0; kb < (K_ITERS - 1) / 3; kb++) {
        #pragma unroll
        for (int j = 0; j < 3; j++) {
            SUBIT(0, j, (j + 1) % 3, 1);
            SUBIT(1, j, (j + 1) % 3, 1);
            SUBIT(2, j, (j + 1) % 3, 1);
            SUBIT(3, j, (j + 1) % 3, 1);
            SUBIT(4, j, (j + 1) % 3, 1);
            SUBIT(5, j, (j + 1) % 3, 1);
            cp_wait0();
            __syncthreads();
            if (kload < K_DIM) {
                LOAD_STAGE_S((j + 2) % 3, kload);
                kload += K_ELE;
            }
            SUBIT(6, j, (j + 1) % 3, 1);
            SUBIT(7, j, (j + 1) % 3, 1);
        }
    }
    // tail: ks = 63, stage 0; nothing pending, no barrier needed
    SUBIT(0, 0, 1, 0);
    SUBIT(1, 0, 1, 0);
    SUBIT(2, 0, 1, 0);
    SUBIT(3, 0, 1, 0);
    SUBIT(4, 0, 1, 0);
    SUBIT(5, 0, 1, 0);
    SUBIT(6, 0, 1, 0);
    SUBIT(7, 0, 1, 0);

    // epilogue: c0,c1 at (row=lane>>2, col=(lane&3)*2+{0,1}); c2,c3 at row+8
    const int erow = lane >> 2;
    const int ecol = (lane & 3) * 2;
    #pragma unroll
    for (int mi = 0; mi < 4; mi++) {
        #pragma unroll
        for (int ni = 0; ni < 4; ni++) {
            const int gc = wn + ni * 8 + ecol;
            const float b0 = rbias[gc], b1 = rbias[gc + 1];
            {
                const int gr = m0 + wm + mi * 16 + erow;
                float2 v;
                v.x = acc[mi][ni][0] + b0;
                v.y = acc[mi][ni][1] + b1;
                *reinterpret_cast<float2*>(out + (size_t)gr * N_DIM + n0 + gc) = v;
            }
            {
                const int gr = m0 + wm + mi * 16 + 8 + erow;
                float2 v;
                v.x = acc[mi][ni][2] + b0;
                v.y = acc[mi][ni][3] + b1;
                *reinterpret_cast<float2*>(out + (size_t)gr * N_DIM + n0 + gc) = v;
            }
        }
    }
}

// ---------------------------------------------------------------- launch
extern "C" void kernel_launch(void* const* d_in, const int* in_sizes, int n_in,
                              void* d_out, int out_size) {
    int xi = 0, bi = 0;
    for (int i = 1; i < n_in; i++) {
        if (in_sizes[i] > in_sizes[xi]) xi = i;
        if (in_sizes[i] < in_sizes[bi]) bi = i;
    }
    int wi = 3 - xi - bi;

    const int*   x32  = (const int*)d_in[xi];
    const int*   w32  = (const int*)d_in[wi];
    const float* bias = (const float*)d_in[bi];
    float* out = (float*)d_out;

    __half* xh = nullptr; cudaGetSymbolAddress((void**)&xh, g_xh);
    __half* wh = nullptr; cudaGetSymbolAddress((void**)&wh, g_wh);

    const int n8x = (M_DIM * K_DIM) / 8;
    const int n8w = (N_DIM * K_DIM) / 8;
    const int n8t = n8x + n8w;
    pack_s32_to_f16<<<(n8t + 255) / 256, 256>>>(x32, w32, xh, wh, n8x, n8t);

    cudaFuncSetAttribute(w8a8_hmma_kernel,
                         cudaFuncAttributeMaxDynamicSharedMemorySize, SMEM_TOTAL);

    dim3 grid(N_DIM / N_TILE, M_DIM / M_TILE);         // (32, 64) = 2048 CTAs
    w8a8_hmma_kernel<<<grid, NTHREADS, SMEM_TOTAL>>>(bias, out);
}